// round 11
// baseline (speedup 1.0000x reference)
#include <cuda_runtime.h>
#include <cstdint>

#define N_POS   4096
#define HEADS   4
#define DHEAD   32
#define C_IN    256
#define HID     128          // HEADS*DHEAD
#define BATCH   4
#define SCALE   10.0f

// Scratch (no cudaMalloc allowed): qkv [b][3*128][n], attn-out [b][128][n]
__device__ float g_qkv[(size_t)BATCH * 3 * HID * N_POS];   // 25.2 MB
__device__ float g_att[(size_t)BATCH * HID * N_POS];       //  8.4 MB

#define FULLM  0xffffffffu

__device__ __forceinline__ uint32_t f2tf(float x) {
    uint32_t r;
    asm("cvt.rna.tf32.f32 %0, %1;" : "=r"(r) : "f"(x));
    return r;
}

__device__ __forceinline__ void mma_tf32(float d[4], const uint32_t a[4],
                                         const uint32_t b[2]) {
    asm volatile(
        "mma.sync.aligned.m16n8k8.row.col.f32.tf32.tf32.f32 "
        "{%0,%1,%2,%3}, {%4,%5,%6,%7}, {%8,%9}, {%0,%1,%2,%3};"
        : "+f"(d[0]), "+f"(d[1]), "+f"(d[2]), "+f"(d[3])
        : "r"(a[0]), "r"(a[1]), "r"(a[2]), "r"(a[3]), "r"(b[0]), "r"(b[1]));
}

__device__ __forceinline__ void cp_async16(void* smem_dst, const void* gsrc) {
    uint32_t s = (uint32_t)__cvta_generic_to_shared(smem_dst);
    asm volatile("cp.async.cg.shared.global [%0], [%1], 16;\n"
                 :: "r"(s), "l"(gsrc) : "memory");
}
__device__ __forceinline__ void cp_commit() {
    asm volatile("cp.async.commit_group;\n" ::: "memory");
}
__device__ __forceinline__ void cp_wait0() {
    asm volatile("cp.async.wait_group 0;\n" ::: "memory");
}

// ---------------------------------------------------------------------------
// Pipelined tensor-core projection GEMM, 3-term tf32 split (fp32 accuracy).
// 2-stage cp.async ring, ONE __syncthreads per k-tile. Raw fp32 staged;
// hi/lo split at fragment load. Optional fused L2-norm over 32-row groups
// (per column) for the q/k sections of the qkv output.
// ---------------------------------------------------------------------------
#define WS_STR 20
#define XS_STR 72

template <bool DO_NORM>
__device__ __forceinline__ void gemm_tc_body(
    const float* __restrict__ W, const float* __restrict__ X,
    float* __restrict__ Y, const float* __restrict__ bias,
    int K, long xstride_b, long ystride_b)
{
    __shared__ float Ws[2][64 * WS_STR];
    __shared__ float Xs[2][16 * XS_STR];
    __shared__ float nrm[128];            // [group 0..1][col 0..63]

    const int b  = blockIdx.z;
    const int o0 = blockIdx.y * 64;
    const int i0 = blockIdx.x * 64;
    const float* Xb = X + (long)b * xstride_b;
    float*       Yb = Y + (long)b * ystride_b;

    const int tid  = threadIdx.x;
    const int wid  = tid >> 5;
    const int lane = tid & 31;
    const int gid  = lane >> 2;
    const int tig  = lane & 3;
    const int wq   = wid >> 1;
    const int wn   = wid & 1;

    const int wo = tid >> 2;              // staging: W row (0..63)
    const int wc = (tid & 3) * 4;         // staging: W col group
    const int xc = tid >> 4;              // staging: X row (0..15)
    const int xi = (tid & 15) * 4;        // staging: X col group

    const int KT = K / 16;

    // prologue: stage k-tile 0
    cp_async16(&Ws[0][wo * WS_STR + wc], &W[(long)(o0 + wo) * K + wc]);
    cp_async16(&Xs[0][xc * XS_STR + xi], &Xb[(long)xc * N_POS + i0 + xi]);
    cp_commit();

    if (DO_NORM && tid < 128) nrm[tid] = 0.0f;

    float acc[4][4] = {};

    for (int kt = 0; kt < KT; kt++) {
        const int s = kt & 1;
        cp_wait0();
        __syncthreads();                  // tile kt visible; prior compute done
        if (kt + 1 < KT) {
            const int k0 = (kt + 1) * 16;
            cp_async16(&Ws[s ^ 1][wo * WS_STR + wc],
                       &W[(long)(o0 + wo) * K + k0 + wc]);
            cp_async16(&Xs[s ^ 1][xc * XS_STR + xi],
                       &Xb[(long)(k0 + xc) * N_POS + i0 + xi]);
            cp_commit();
        }

        #pragma unroll
        for (int kk = 0; kk < 2; kk++) {
            const int ar = wq * 16 + gid;
            const int ac = kk * 8 + tig;
            float w0 = Ws[s][ar * WS_STR + ac];
            float w1 = Ws[s][(ar + 8) * WS_STR + ac];
            float w2 = Ws[s][ar * WS_STR + ac + 4];
            float w3 = Ws[s][(ar + 8) * WS_STR + ac + 4];
            uint32_t aH[4], aL[4];
            aH[0] = f2tf(w0); aL[0] = f2tf(w0 - __uint_as_float(aH[0]));
            aH[1] = f2tf(w1); aL[1] = f2tf(w1 - __uint_as_float(aH[1]));
            aH[2] = f2tf(w2); aL[2] = f2tf(w2 - __uint_as_float(aH[2]));
            aH[3] = f2tf(w3); aL[3] = f2tf(w3 - __uint_as_float(aH[3]));
            #pragma unroll
            for (int nt = 0; nt < 4; nt++) {
                const int col = wn * 32 + nt * 8 + gid;
                const int cr  = kk * 8 + tig;
                float x0 = Xs[s][cr * XS_STR + col];
                float x1 = Xs[s][(cr + 4) * XS_STR + col];
                uint32_t bH[2], bL[2];
                bH[0] = f2tf(x0); bL[0] = f2tf(x0 - __uint_as_float(bH[0]));
                bH[1] = f2tf(x1); bL[1] = f2tf(x1 - __uint_as_float(bH[1]));
                mma_tf32(acc[nt], aH, bH);
                mma_tf32(acc[nt], aH, bL);
                mma_tf32(acc[nt], aL, bH);
            }
        }
    }

    if (DO_NORM && o0 < 2 * HID) {
        // fused L2-norm: sum of squares over each 32-row (d) group, per column
        const int g = wq >> 1;
        float p0[4], p1[4];
        #pragma unroll
        for (int nt = 0; nt < 4; nt++) {
            p0[nt] = acc[nt][0] * acc[nt][0] + acc[nt][2] * acc[nt][2];
            p1[nt] = acc[nt][1] * acc[nt][1] + acc[nt][3] * acc[nt][3];
            #pragma unroll
            for (int m = 4; m < 32; m <<= 1) {
                p0[nt] += __shfl_xor_sync(FULLM, p0[nt], m);
                p1[nt] += __shfl_xor_sync(FULLM, p1[nt], m);
            }
        }
        if (lane < 4) {
            #pragma unroll
            for (int nt = 0; nt < 4; nt++) {
                const int col = wn * 32 + nt * 8 + 2 * tig;
                atomicAdd(&nrm[g * 64 + col],     p0[nt]);
                atomicAdd(&nrm[g * 64 + col + 1], p1[nt]);
            }
        }
        __syncthreads();
        #pragma unroll
        for (int nt = 0; nt < 4; nt++) {
            const int col = wn * 32 + nt * 8 + 2 * tig;
            float i0v = 1.0f / fmaxf(sqrtf(nrm[g * 64 + col]),     1e-12f);
            float i1v = 1.0f / fmaxf(sqrtf(nrm[g * 64 + col + 1]), 1e-12f);
            acc[nt][0] *= i0v; acc[nt][2] *= i0v;
            acc[nt][1] *= i1v; acc[nt][3] *= i1v;
        }
    }

    const int orow = o0 + wq * 16 + gid;
    const float b0 = bias ? bias[orow]     : 0.0f;
    const float b1 = bias ? bias[orow + 8] : 0.0f;
    #pragma unroll
    for (int nt = 0; nt < 4; nt++) {
        const int col = i0 + wn * 32 + nt * 8 + 2 * tig;
        float2 lo, hi;
        lo.x = acc[nt][0] + b0; lo.y = acc[nt][1] + b0;
        hi.x = acc[nt][2] + b1; hi.y = acc[nt][3] + b1;
        *(float2*)&Yb[(long)orow * N_POS + col]       = lo;
        *(float2*)&Yb[(long)(orow + 8) * N_POS + col] = hi;
    }
}

__global__ __launch_bounds__(256) void gemm_qkv_kernel(
    const float* __restrict__ W, const float* __restrict__ X)
{
    gemm_tc_body<true>(W, X, g_qkv, nullptr, C_IN,
                       (long)C_IN * N_POS, (long)3 * HID * N_POS);
}

__global__ __launch_bounds__(256) void gemm_out_kernel(
    const float* __restrict__ W, float* __restrict__ Y,
    const float* __restrict__ bias)
{
    gemm_tc_body<false>(W, g_att, Y, bias, HID,
                        (long)HID * N_POS, (long)C_IN * N_POS);
}

// ---------------------------------------------------------------------------
// Tensor-core flash attention, q-tile 128, single-sync 2-stage cp.async ring.
// K/V tiles are 32 d-rows x 64 j-cols: TWO cp_async16 per thread per array
// (512 slots / 256 threads) — this was the round-10 bug (half-staged tile).
// ---------------------------------------------------------------------------
#define KS_STR 72     // b-frag bank = 8*tig+gid, distinct
#define VS_STR 68     // b-frag bank = 4*gid+tig, distinct
#define OS_STR 136
#define PB_STR 33
#define STG_WORDS (32 * KS_STR + 32 * VS_STR)   // 4480 floats per stage

__device__ __forceinline__ float quad_col(float pe, float po, int srcTig, int parity) {
    float xe = __shfl_sync(FULLM, pe, srcTig, 4);
    float xo = __shfl_sync(FULLM, po, srcTig, 4);
    return parity ? xo : xe;
}

__global__ __launch_bounds__(256, 2) void attn_tc_kernel()
{
    __shared__ float SB[2 * STG_WORDS];   // K/V ring; aliased by epilogue
    __shared__ float sh_l[128];

    const int b   = blockIdx.z;
    const int h   = blockIdx.y;
    const int q0  = blockIdx.x * 128;
    const int tid = threadIdx.x;
    const int wid  = tid >> 5;
    const int lane = tid & 31;
    const int gid  = lane >> 2;
    const int tig  = lane & 3;
    const int wq   = wid >> 1;   // 0..3 : 32-row q group
    const int wn   = wid & 1;    // 0..1 : j/k half

    const float* qb = g_qkv + ((long)(b * 3 + 0) * HID + h * DHEAD) * N_POS;
    const float* kb = g_qkv + ((long)(b * 3 + 1) * HID + h * DHEAD) * N_POS;
    const float* vb = g_qkv + ((long)(b * 3 + 2) * HID + h * DHEAD) * N_POS;

    // prologue: stage tile 0 (full 32x64 tiles: 2 issues per thread per array)
    #pragma unroll
    for (int r = 0; r < 2; r++) {
        int c = tid + r * 256;
        int d = c >> 4, j4 = (c & 15) * 4;
        cp_async16(SB + d * KS_STR + j4,               kb + (long)d * N_POS + j4);
        cp_async16(SB + 32 * KS_STR + d * VS_STR + j4, vb + (long)d * N_POS + j4);
    }
    cp_commit();

    // Q fragments in registers (one-time)
    uint32_t qf[2][4][4];
    #pragma unroll
    for (int mt = 0; mt < 2; mt++) {
        const int row = wq * 32 + mt * 16 + gid;
        const float* qp = qb + q0 + row;
        #pragma unroll
        for (int kk = 0; kk < 4; kk++) {
            qf[mt][kk][0] = f2tf(qp[(long)(kk * 8 + tig) * N_POS]);
            qf[mt][kk][1] = f2tf(qp[(long)(kk * 8 + tig) * N_POS + 8]);
            qf[mt][kk][2] = f2tf(qp[(long)(kk * 8 + tig + 4) * N_POS]);
            qf[mt][kk][3] = f2tf(qp[(long)(kk * 8 + tig + 4) * N_POS + 8]);
        }
    }
    if (tid < 128) sh_l[tid] = 0.0f;

    float O[2][4][4] = {};
    float l_lo[2] = {}, l_hi[2] = {};

    const int srcA = tig >> 1;
    const int srcB = srcA + 2;
    const int par  = tig & 1;

    for (int it = 0; it < N_POS / 64; it++) {
        const int s = it & 1;
        float* KsS = SB + s * STG_WORDS;
        float* VsS = KsS + 32 * KS_STR;

        cp_wait0();
        __syncthreads();   // tile it visible; prior-iter compute done

        if (it + 1 < N_POS / 64) {
            const int j0 = (it + 1) * 64;
            float* Kn = SB + (s ^ 1) * STG_WORDS;
            float* Vn = Kn + 32 * KS_STR;
            #pragma unroll
            for (int r = 0; r < 2; r++) {
                int c = tid + r * 256;
                int d = c >> 4, j4 = (c & 15) * 4;
                cp_async16(Kn + d * KS_STR + j4, kb + (long)d * N_POS + j0 + j4);
                cp_async16(Vn + d * VS_STR + j4, vb + (long)d * N_POS + j0 + j4);
            }
            cp_commit();
        }

        // ---- GEMM1: S[32q x 32j] = Q K' ----
        float S[2][4][4] = {};
        #pragma unroll
        for (int kk = 0; kk < 4; kk++) {
            const int c0 = kk * 8 + tig;
            #pragma unroll
            for (int nt = 0; nt < 4; nt++) {
                const int col = wn * 32 + nt * 8 + gid;
                uint32_t bb[2];
                bb[0] = f2tf(KsS[c0 * KS_STR + col]);
                bb[1] = f2tf(KsS[(c0 + 4) * KS_STR + col]);
                mma_tf32(S[0][nt], qf[0][kk], bb);
                mma_tf32(S[1][nt], qf[1][kk], bb);
            }
        }

        // ---- P = exp(10S - 10); accumulate l ----
        #pragma unroll
        for (int mt = 0; mt < 2; mt++)
            #pragma unroll
            for (int nt = 0; nt < 4; nt++) {
                S[mt][nt][0] = __expf(fmaf(S[mt][nt][0], SCALE, -SCALE));
                S[mt][nt][1] = __expf(fmaf(S[mt][nt][1], SCALE, -SCALE));
                S[mt][nt][2] = __expf(fmaf(S[mt][nt][2], SCALE, -SCALE));
                S[mt][nt][3] = __expf(fmaf(S[mt][nt][3], SCALE, -SCALE));
                l_lo[mt] += S[mt][nt][0] + S[mt][nt][1];
                l_hi[mt] += S[mt][nt][2] + S[mt][nt][3];
            }

        // ---- GEMM2: O += P V' (this warp's 32-k half) ----
        #pragma unroll
        for (int nt = 0; nt < 4; nt++) {
            uint32_t a0[4], a1[4];
            a0[0] = f2tf(quad_col(S[0][nt][0], S[0][nt][1], srcA, par));
            a0[1] = f2tf(quad_col(S[0][nt][2], S[0][nt][3], srcA, par));
            a0[2] = f2tf(quad_col(S[0][nt][0], S[0][nt][1], srcB, par));
            a0[3] = f2tf(quad_col(S[0][nt][2], S[0][nt][3], srcB, par));
            a1[0] = f2tf(quad_col(S[1][nt][0], S[1][nt][1], srcA, par));
            a1[1] = f2tf(quad_col(S[1][nt][2], S[1][nt][3], srcA, par));
            a1[2] = f2tf(quad_col(S[1][nt][0], S[1][nt][1], srcB, par));
            a1[3] = f2tf(quad_col(S[1][nt][2], S[1][nt][3], srcB, par));
            const int kbase = wn * 32 + nt * 8;
            #pragma unroll
            for (int dt = 0; dt < 4; dt++) {
                const int dcol = dt * 8 + gid;
                uint32_t bb[2];
                bb[0] = f2tf(VsS[dcol * VS_STR + kbase + tig]);
                bb[1] = f2tf(VsS[dcol * VS_STR + kbase + tig + 4]);
                mma_tf32(O[0][dt], a0, bb);
                mma_tf32(O[1][dt], a1, bb);
            }
        }
    }

    // ---- reduce l ----
    #pragma unroll
    for (int mt = 0; mt < 2; mt++) {
        l_lo[mt] += __shfl_xor_sync(FULLM, l_lo[mt], 1);
        l_lo[mt] += __shfl_xor_sync(FULLM, l_lo[mt], 2);
        l_hi[mt] += __shfl_xor_sync(FULLM, l_hi[mt], 1);
        l_hi[mt] += __shfl_xor_sync(FULLM, l_hi[mt], 2);
        if (tig == 0) {
            atomicAdd(&sh_l[wq * 32 + mt * 16 + gid],     l_lo[mt]);
            atomicAdd(&sh_l[wq * 32 + mt * 16 + gid + 8], l_hi[mt]);
        }
    }
    __syncthreads();   // l complete; all warps past ring reads

    // ---- merge k-half partials via smem (aliases the K/V ring) ----
    float* Os = SB;                 // [32 d][OS_STR]
    float* PB = SB + 32 * OS_STR;   // [128 q][PB_STR]

    if (wn == 1) {
        #pragma unroll
        for (int mt = 0; mt < 2; mt++) {
            const int row = wq * 32 + mt * 16 + gid;
            #pragma unroll
            for (int nt = 0; nt < 4; nt++) {
                const int col = nt * 8 + 2 * tig;
                PB[row * PB_STR + col]           = O[mt][nt][0];
                PB[row * PB_STR + col + 1]       = O[mt][nt][1];
                PB[(row + 8) * PB_STR + col]     = O[mt][nt][2];
                PB[(row + 8) * PB_STR + col + 1] = O[mt][nt][3];
            }
        }
    }
    __syncthreads();
    if (wn == 0) {
        #pragma unroll
        for (int mt = 0; mt < 2; mt++) {
            const int row = wq * 32 + mt * 16 + gid;
            const float invl_lo = 1.0f / sh_l[row];
            const float invl_hi = 1.0f / sh_l[row + 8];
            #pragma unroll
            for (int nt = 0; nt < 4; nt++) {
                const int col = nt * 8 + 2 * tig;
                float o0 = (O[mt][nt][0] + PB[row * PB_STR + col])           * invl_lo;
                float o1 = (O[mt][nt][1] + PB[row * PB_STR + col + 1])       * invl_lo;
                float o2 = (O[mt][nt][2] + PB[(row + 8) * PB_STR + col])     * invl_hi;
                float o3 = (O[mt][nt][3] + PB[(row + 8) * PB_STR + col + 1]) * invl_hi;
                Os[col * OS_STR + row]           = o0;
                Os[(col + 1) * OS_STR + row]     = o1;
                Os[col * OS_STR + row + 8]       = o2;
                Os[(col + 1) * OS_STR + row + 8] = o3;
            }
        }
    }
    __syncthreads();

    float* ob = g_att + ((long)b * HID + h * DHEAD) * N_POS + q0;
    #pragma unroll
    for (int r = 0; r < 16; r++) {
        int idx = tid + r * 256;
        int d = idx >> 7, qi = idx & 127;
        ob[(long)d * N_POS + qi] = Os[d * OS_STR + qi];
    }
}

// ---------------------------------------------------------------------------
extern "C" void kernel_launch(void* const* d_in, const int* in_sizes, int n_in,
                              void* d_out, int out_size)
{
    const float* x     = (const float*)d_in[0];   // [4,256,64,64]
    const float* w_qkv = (const float*)d_in[1];   // [384,256]
    const float* w_out = (const float*)d_in[2];   // [256,128]
    const float* b_out = (const float*)d_in[3];   // [256]
    float* y = (float*)d_out;                     // [4,256,64,64]

    // A: qkv = w_qkv @ x   (pipelined tf32 split MMA + fused q/k L2-norm)
    {
        dim3 grid(N_POS / 64, (3 * HID) / 64, BATCH);
        gemm_qkv_kernel<<<grid, 256>>>(w_qkv, x);
    }
    // B: tensor-core flash attention (q-tile 128)
    {
        dim3 grid(N_POS / 128, HEADS, BATCH);
        attn_tc_kernel<<<grid, 256>>>();
    }
    // C: y = w_out @ att + b_out   (pipelined tf32 split MMA)
    {
        dim3 grid(N_POS / 64, C_IN / 64, BATCH);
        gemm_out_kernel<<<grid, 256>>>(w_out, y, b_out);
    }
}

// round 12
// speedup vs baseline: 1.0350x; 1.0350x over previous
#include <cuda_runtime.h>
#include <cstdint>

#define N_POS   4096
#define HEADS   4
#define DHEAD   32
#define C_IN    256
#define HID     128          // HEADS*DHEAD
#define BATCH   4
#define SCALE   10.0f

// Scratch (no cudaMalloc allowed): qkv [b][3*128][n], attn-out [b][128][n]
__device__ float g_qkv[(size_t)BATCH * 3 * HID * N_POS];   // 25.2 MB
__device__ float g_att[(size_t)BATCH * HID * N_POS];       //  8.4 MB

#define FULLM  0xffffffffu

__device__ __forceinline__ uint32_t f2tf(float x) {
    uint32_t r;
    asm("cvt.rna.tf32.f32 %0, %1;" : "=r"(r) : "f"(x));
    return r;
}

__device__ __forceinline__ void mma_tf32(float d[4], const uint32_t a[4],
                                         const uint32_t b[2]) {
    asm volatile(
        "mma.sync.aligned.m16n8k8.row.col.f32.tf32.tf32.f32 "
        "{%0,%1,%2,%3}, {%4,%5,%6,%7}, {%8,%9}, {%0,%1,%2,%3};"
        : "+f"(d[0]), "+f"(d[1]), "+f"(d[2]), "+f"(d[3])
        : "r"(a[0]), "r"(a[1]), "r"(a[2]), "r"(a[3]), "r"(b[0]), "r"(b[1]));
}

__device__ __forceinline__ void cp_async16(void* smem_dst, const void* gsrc) {
    uint32_t s = (uint32_t)__cvta_generic_to_shared(smem_dst);
    asm volatile("cp.async.cg.shared.global [%0], [%1], 16;\n"
                 :: "r"(s), "l"(gsrc) : "memory");
}

// ---------------------------------------------------------------------------
// Projection GEMM: tensor-core, 3-term tf32 split done ONCE at staging,
// register double-buffer prefetch hides LDG latency, one sync per k-tile.
//   Y[b][o][i] = sum_c W[o][c] X[b][c][i] (+ bias[o])
// Block 256 thr, out tile 64(o) x 64(i); warp tile 16(o) x 32(i); k-tile 16.
// Optional fused L2-norm over 32-row (d) groups for the q/k outputs.
// ---------------------------------------------------------------------------
#define WS_STR 20
#define XS_STR 72

template <bool DO_NORM>
__device__ __forceinline__ void gemm_tc_body(
    const float* __restrict__ W, const float* __restrict__ X,
    float* __restrict__ Y, const float* __restrict__ bias,
    int K, long xstride_b, long ystride_b)
{
    __shared__ uint32_t WsH[2][64 * WS_STR], WsL[2][64 * WS_STR];
    __shared__ uint32_t XsH[2][16 * XS_STR], XsL[2][16 * XS_STR];
    __shared__ float nrm[128];            // [group 0..1][col 0..63]

    const int b  = blockIdx.z;
    const int o0 = blockIdx.y * 64;
    const int i0 = blockIdx.x * 64;
    const float* Xb = X + (long)b * xstride_b;
    float*       Yb = Y + (long)b * ystride_b;

    const int tid  = threadIdx.x;
    const int wid  = tid >> 5;
    const int lane = tid & 31;
    const int gid  = lane >> 2;
    const int tig  = lane & 3;
    const int wq   = wid >> 1;
    const int wn   = wid & 1;

    const int wo = tid >> 2;              // staging: W row (0..63)
    const int wc = (tid & 3) * 4;         // staging: W col group
    const int xc = tid >> 4;              // staging: X row (0..15)
    const int xi = (tid & 15) * 4;        // staging: X col group

    const int KT = K / 16;

    float4 wreg, xreg;

    // split-and-store tile data held in (wreg, xreg) into smem buffer s
    auto stage_split = [&](int s) {
        uint4 h, l;
        h.x = f2tf(wreg.x); l.x = f2tf(wreg.x - __uint_as_float(h.x));
        h.y = f2tf(wreg.y); l.y = f2tf(wreg.y - __uint_as_float(h.y));
        h.z = f2tf(wreg.z); l.z = f2tf(wreg.z - __uint_as_float(h.z));
        h.w = f2tf(wreg.w); l.w = f2tf(wreg.w - __uint_as_float(h.w));
        *(uint4*)&WsH[s][wo * WS_STR + wc] = h;
        *(uint4*)&WsL[s][wo * WS_STR + wc] = l;
        h.x = f2tf(xreg.x); l.x = f2tf(xreg.x - __uint_as_float(h.x));
        h.y = f2tf(xreg.y); l.y = f2tf(xreg.y - __uint_as_float(h.y));
        h.z = f2tf(xreg.z); l.z = f2tf(xreg.z - __uint_as_float(h.z));
        h.w = f2tf(xreg.w); l.w = f2tf(xreg.w - __uint_as_float(h.w));
        *(uint4*)&XsH[s][xc * XS_STR + xi] = h;
        *(uint4*)&XsL[s][xc * XS_STR + xi] = l;
    };
    auto load_tile = [&](int kt) {
        const int k0 = kt * 16;
        wreg = *(const float4*)&W[(long)(o0 + wo) * K + k0 + wc];
        xreg = *(const float4*)&Xb[(long)(k0 + xc) * N_POS + i0 + xi];
    };

    // prologue: tile 0 staged, tile 1 in regs
    load_tile(0);
    stage_split(0);
    if (KT > 1) load_tile(1);
    if (DO_NORM && tid < 128) nrm[tid] = 0.0f;
    __syncthreads();

    float acc[4][4] = {};

    for (int kt = 0; kt < KT; kt++) {
        const int s = kt & 1;
        if (kt + 1 < KT) {
            stage_split(s ^ 1);               // STS tile kt+1 (regs -> smem)
            if (kt + 2 < KT) load_tile(kt + 2);  // LDG tile kt+2 -> regs
        }

        #pragma unroll
        for (int kk = 0; kk < 2; kk++) {
            const int ar = wq * 16 + gid;
            const int ac = kk * 8 + tig;
            uint32_t aH[4], aL[4];
            aH[0] = WsH[s][ar * WS_STR + ac];
            aH[1] = WsH[s][(ar + 8) * WS_STR + ac];
            aH[2] = WsH[s][ar * WS_STR + ac + 4];
            aH[3] = WsH[s][(ar + 8) * WS_STR + ac + 4];
            aL[0] = WsL[s][ar * WS_STR + ac];
            aL[1] = WsL[s][(ar + 8) * WS_STR + ac];
            aL[2] = WsL[s][ar * WS_STR + ac + 4];
            aL[3] = WsL[s][(ar + 8) * WS_STR + ac + 4];
            #pragma unroll
            for (int nt = 0; nt < 4; nt++) {
                const int col = wn * 32 + nt * 8 + gid;
                const int cr  = kk * 8 + tig;
                uint32_t bH[2], bL[2];
                bH[0] = XsH[s][cr * XS_STR + col];
                bH[1] = XsH[s][(cr + 4) * XS_STR + col];
                bL[0] = XsL[s][cr * XS_STR + col];
                bL[1] = XsL[s][(cr + 4) * XS_STR + col];
                mma_tf32(acc[nt], aH, bH);
                mma_tf32(acc[nt], aH, bL);
                mma_tf32(acc[nt], aL, bH);
            }
        }
        __syncthreads();
    }

    if (DO_NORM && o0 < 2 * HID) {
        // fused L2-norm: sum of squares over each 32-row (d) group, per column
        const int g = wq >> 1;
        float p0[4], p1[4];
        #pragma unroll
        for (int nt = 0; nt < 4; nt++) {
            p0[nt] = acc[nt][0] * acc[nt][0] + acc[nt][2] * acc[nt][2];
            p1[nt] = acc[nt][1] * acc[nt][1] + acc[nt][3] * acc[nt][3];
            #pragma unroll
            for (int m = 4; m < 32; m <<= 1) {
                p0[nt] += __shfl_xor_sync(FULLM, p0[nt], m);
                p1[nt] += __shfl_xor_sync(FULLM, p1[nt], m);
            }
        }
        if (lane < 4) {
            #pragma unroll
            for (int nt = 0; nt < 4; nt++) {
                const int col = wn * 32 + nt * 8 + 2 * tig;
                atomicAdd(&nrm[g * 64 + col],     p0[nt]);
                atomicAdd(&nrm[g * 64 + col + 1], p1[nt]);
            }
        }
        __syncthreads();
        #pragma unroll
        for (int nt = 0; nt < 4; nt++) {
            const int col = wn * 32 + nt * 8 + 2 * tig;
            float i0v = 1.0f / fmaxf(sqrtf(nrm[g * 64 + col]),     1e-12f);
            float i1v = 1.0f / fmaxf(sqrtf(nrm[g * 64 + col + 1]), 1e-12f);
            acc[nt][0] *= i0v; acc[nt][2] *= i0v;
            acc[nt][1] *= i1v; acc[nt][3] *= i1v;
        }
    }

    const int orow = o0 + wq * 16 + gid;
    const float b0 = bias ? bias[orow]     : 0.0f;
    const float b1 = bias ? bias[orow + 8] : 0.0f;
    #pragma unroll
    for (int nt = 0; nt < 4; nt++) {
        const int col = i0 + wn * 32 + nt * 8 + 2 * tig;
        float2 lo, hi;
        lo.x = acc[nt][0] + b0; lo.y = acc[nt][1] + b0;
        hi.x = acc[nt][2] + b1; hi.y = acc[nt][3] + b1;
        *(float2*)&Yb[(long)orow * N_POS + col]       = lo;
        *(float2*)&Yb[(long)(orow + 8) * N_POS + col] = hi;
    }
}

__global__ __launch_bounds__(256) void gemm_qkv_kernel(
    const float* __restrict__ W, const float* __restrict__ X)
{
    gemm_tc_body<true>(W, X, g_qkv, nullptr, C_IN,
                       (long)C_IN * N_POS, (long)3 * HID * N_POS);
}

__global__ __launch_bounds__(256) void gemm_out_kernel(
    const float* __restrict__ W, float* __restrict__ Y,
    const float* __restrict__ bias)
{
    gemm_tc_body<false>(W, g_att, Y, bias, HID,
                        (long)HID * N_POS, (long)C_IN * N_POS);
}

// ---------------------------------------------------------------------------
// Tensor-core flash attention (round-9 mainloop: 2-stage ring, wait_group 1,
// refill at iteration end => prefetch distance 2).
//  - Q fragments in registers; fixed softmax shift +10; P in regs via quad
//    shuffle-transpose; each warp 32 q-rows x 32 j-cols.
// Block = (b, h, 128-query tile), 8 warps (wq 0..3 x wn 0..1), 512 blocks.
// ---------------------------------------------------------------------------
#define KS_STR 72     // b-frag bank = 8*tig+gid, distinct
#define VS_STR 68     // b-frag bank = 4*gid+tig, distinct
#define OS_STR 136
#define PB_STR 33
#define STG_WORDS (32 * KS_STR + 32 * VS_STR)   // 4480 floats per stage

__device__ __forceinline__ float quad_col(float pe, float po, int srcTig, int parity) {
    float xe = __shfl_sync(FULLM, pe, srcTig, 4);
    float xo = __shfl_sync(FULLM, po, srcTig, 4);
    return parity ? xo : xe;
}

__global__ __launch_bounds__(256, 2) void attn_tc_kernel()
{
    __shared__ float SB[2 * STG_WORDS];   // K/V ring; aliased by epilogue
    __shared__ float sh_l[128];

    const int b   = blockIdx.z;
    const int h   = blockIdx.y;
    const int q0  = blockIdx.x * 128;
    const int tid = threadIdx.x;
    const int wid  = tid >> 5;
    const int lane = tid & 31;
    const int gid  = lane >> 2;
    const int tig  = lane & 3;
    const int wq   = wid >> 1;   // 0..3 : 32-row q group
    const int wn   = wid & 1;    // 0..1 : j/k half

    const float* qb = g_qkv + ((long)(b * 3 + 0) * HID + h * DHEAD) * N_POS;
    const float* kb = g_qkv + ((long)(b * 3 + 1) * HID + h * DHEAD) * N_POS;
    const float* vb = g_qkv + ((long)(b * 3 + 2) * HID + h * DHEAD) * N_POS;

    float* Ks0 = SB;
    float* Vs0 = SB + 32 * KS_STR;
    float* Ks1 = SB + STG_WORDS;
    float* Vs1 = SB + STG_WORDS + 32 * KS_STR;

    // ---- stage tiles 0 and 1 (full 32x64 tiles: 2 issues/thread/array) ----
    #pragma unroll
    for (int r = 0; r < 2; r++) {
        int c = tid + r * 256;
        int d = c >> 4, j4 = (c & 15) * 4;
        cp_async16(Ks0 + d * KS_STR + j4, kb + (long)d * N_POS + j4);
        cp_async16(Vs0 + d * VS_STR + j4, vb + (long)d * N_POS + j4);
    }
    asm volatile("cp.async.commit_group;\n" ::: "memory");
    #pragma unroll
    for (int r = 0; r < 2; r++) {
        int c = tid + r * 256;
        int d = c >> 4, j4 = (c & 15) * 4;
        cp_async16(Ks1 + d * KS_STR + j4, kb + (long)d * N_POS + 64 + j4);
        cp_async16(Vs1 + d * VS_STR + j4, vb + (long)d * N_POS + 64 + j4);
    }
    asm volatile("cp.async.commit_group;\n" ::: "memory");

    // ---- Q fragments in registers (one-time) ----
    uint32_t qf[2][4][4];
    #pragma unroll
    for (int mt = 0; mt < 2; mt++) {
        const int row = wq * 32 + mt * 16 + gid;
        const float* qp = qb + q0 + row;
        #pragma unroll
        for (int kk = 0; kk < 4; kk++) {
            qf[mt][kk][0] = f2tf(qp[(long)(kk * 8 + tig) * N_POS]);
            qf[mt][kk][1] = f2tf(qp[(long)(kk * 8 + tig) * N_POS + 8]);
            qf[mt][kk][2] = f2tf(qp[(long)(kk * 8 + tig + 4) * N_POS]);
            qf[mt][kk][3] = f2tf(qp[(long)(kk * 8 + tig + 4) * N_POS + 8]);
        }
    }
    if (tid < 128) sh_l[tid] = 0.0f;

    float O[2][4][4] = {};
    float l_lo[2] = {}, l_hi[2] = {};

    const int srcA = tig >> 1;
    const int srcB = srcA + 2;
    const int par  = tig & 1;

    for (int it = 0; it < N_POS / 64; it++) {
        const int s = it & 1;
        float* KsS = s ? Ks1 : Ks0;
        float* VsS = s ? Vs1 : Vs0;

        asm volatile("cp.async.wait_group 1;\n" ::: "memory");
        __syncthreads();   // tile it visible to all; also fences Q/sh_l init

        // ---- GEMM1: S[32q x 32j] = Q K' ----
        float S[2][4][4] = {};
        #pragma unroll
        for (int kk = 0; kk < 4; kk++) {
            const int c0 = kk * 8 + tig;
            #pragma unroll
            for (int nt = 0; nt < 4; nt++) {
                const int col = wn * 32 + nt * 8 + gid;
                uint32_t bb[2];
                bb[0] = f2tf(KsS[c0 * KS_STR + col]);
                bb[1] = f2tf(KsS[(c0 + 4) * KS_STR + col]);
                mma_tf32(S[0][nt], qf[0][kk], bb);
                mma_tf32(S[1][nt], qf[1][kk], bb);
            }
        }

        // ---- P = exp(10S - 10); accumulate l ----
        #pragma unroll
        for (int mt = 0; mt < 2; mt++)
            #pragma unroll
            for (int nt = 0; nt < 4; nt++) {
                S[mt][nt][0] = __expf(fmaf(S[mt][nt][0], SCALE, -SCALE));
                S[mt][nt][1] = __expf(fmaf(S[mt][nt][1], SCALE, -SCALE));
                S[mt][nt][2] = __expf(fmaf(S[mt][nt][2], SCALE, -SCALE));
                S[mt][nt][3] = __expf(fmaf(S[mt][nt][3], SCALE, -SCALE));
                l_lo[mt] += S[mt][nt][0] + S[mt][nt][1];
                l_hi[mt] += S[mt][nt][2] + S[mt][nt][3];
            }

        // ---- GEMM2: O += P V' (this warp's 32-k half) ----
        #pragma unroll
        for (int nt = 0; nt < 4; nt++) {
            uint32_t a0[4], a1[4];
            a0[0] = f2tf(quad_col(S[0][nt][0], S[0][nt][1], srcA, par));
            a0[1] = f2tf(quad_col(S[0][nt][2], S[0][nt][3], srcA, par));
            a0[2] = f2tf(quad_col(S[0][nt][0], S[0][nt][1], srcB, par));
            a0[3] = f2tf(quad_col(S[0][nt][2], S[0][nt][3], srcB, par));
            a1[0] = f2tf(quad_col(S[1][nt][0], S[1][nt][1], srcA, par));
            a1[1] = f2tf(quad_col(S[1][nt][2], S[1][nt][3], srcA, par));
            a1[2] = f2tf(quad_col(S[1][nt][0], S[1][nt][1], srcB, par));
            a1[3] = f2tf(quad_col(S[1][nt][2], S[1][nt][3], srcB, par));
            const int kbase = wn * 32 + nt * 8;
            #pragma unroll
            for (int dt = 0; dt < 4; dt++) {
                const int dcol = dt * 8 + gid;
                uint32_t bb[2];
                bb[0] = f2tf(VsS[dcol * VS_STR + kbase + tig]);
                bb[1] = f2tf(VsS[dcol * VS_STR + kbase + tig + 4]);
                mma_tf32(O[0][dt], a0, bb);
                mma_tf32(O[1][dt], a1, bb);
            }
        }

        __syncthreads();   // all warps done with this stage's smem

        // refill this stage with tile it+2 (or commit an empty group)
        if (it + 2 < N_POS / 64) {
            const int j0 = (it + 2) * 64;
            #pragma unroll
            for (int r = 0; r < 2; r++) {
                int c = tid + r * 256;
                int d = c >> 4, j4 = (c & 15) * 4;
                cp_async16(KsS + d * KS_STR + j4, kb + (long)d * N_POS + j0 + j4);
                cp_async16(VsS + d * VS_STR + j4, vb + (long)d * N_POS + j0 + j4);
            }
        }
        asm volatile("cp.async.commit_group;\n" ::: "memory");
    }

    // ---- reduce l ----
    #pragma unroll
    for (int mt = 0; mt < 2; mt++) {
        l_lo[mt] += __shfl_xor_sync(FULLM, l_lo[mt], 1);
        l_lo[mt] += __shfl_xor_sync(FULLM, l_lo[mt], 2);
        l_hi[mt] += __shfl_xor_sync(FULLM, l_hi[mt], 1);
        l_hi[mt] += __shfl_xor_sync(FULLM, l_hi[mt], 2);
        if (tig == 0) {
            atomicAdd(&sh_l[wq * 32 + mt * 16 + gid],     l_lo[mt]);
            atomicAdd(&sh_l[wq * 32 + mt * 16 + gid + 8], l_hi[mt]);
        }
    }
    __syncthreads();   // l complete; all warps past ring reads

    // ---- merge k-half partials via smem (aliases the K/V ring) ----
    float* Os = SB;                 // [32 d][OS_STR]
    float* PB = SB + 32 * OS_STR;   // [128 q][PB_STR]

    if (wn == 1) {
        #pragma unroll
        for (int mt = 0; mt < 2; mt++) {
            const int row = wq * 32 + mt * 16 + gid;
            #pragma unroll
            for (int nt = 0; nt < 4; nt++) {
                const int col = nt * 8 + 2 * tig;
                PB[row * PB_STR + col]           = O[mt][nt][0];
                PB[row * PB_STR + col + 1]       = O[mt][nt][1];
                PB[(row + 8) * PB_STR + col]     = O[mt][nt][2];
                PB[(row + 8) * PB_STR + col + 1] = O[mt][nt][3];
            }
        }
    }
    __syncthreads();
    if (wn == 0) {
        #pragma unroll
        for (int mt = 0; mt < 2; mt++) {
            const int row = wq * 32 + mt * 16 + gid;
            const float invl_lo = 1.0f / sh_l[row];
            const float invl_hi = 1.0f / sh_l[row + 8];
            #pragma unroll
            for (int nt = 0; nt < 4; nt++) {
                const int col = nt * 8 + 2 * tig;
                float o0 = (O[mt][nt][0] + PB[row * PB_STR + col])           * invl_lo;
                float o1 = (O[mt][nt][1] + PB[row * PB_STR + col + 1])       * invl_lo;
                float o2 = (O[mt][nt][2] + PB[(row + 8) * PB_STR + col])     * invl_hi;
                float o3 = (O[mt][nt][3] + PB[(row + 8) * PB_STR + col + 1]) * invl_hi;
                Os[col * OS_STR + row]           = o0;
                Os[(col + 1) * OS_STR + row]     = o1;
                Os[col * OS_STR + row + 8]       = o2;
                Os[(col + 1) * OS_STR + row + 8] = o3;
            }
        }
    }
    __syncthreads();

    float* ob = g_att + ((long)b * HID + h * DHEAD) * N_POS + q0;
    #pragma unroll
    for (int r = 0; r < 16; r++) {
        int idx = tid + r * 256;
        int d = idx >> 7, qi = idx & 127;
        ob[(long)d * N_POS + qi] = Os[d * OS_STR + qi];
    }
}

// ---------------------------------------------------------------------------
extern "C" void kernel_launch(void* const* d_in, const int* in_sizes, int n_in,
                              void* d_out, int out_size)
{
    const float* x     = (const float*)d_in[0];   // [4,256,64,64]
    const float* w_qkv = (const float*)d_in[1];   // [384,256]
    const float* w_out = (const float*)d_in[2];   // [256,128]
    const float* b_out = (const float*)d_in[3];   // [256]
    float* y = (float*)d_out;                     // [4,256,64,64]

    // A: qkv = w_qkv @ x   (split-at-staging tf32 MMA + fused q/k L2-norm)
    {
        dim3 grid(N_POS / 64, (3 * HID) / 64, BATCH);
        gemm_qkv_kernel<<<grid, 256>>>(w_qkv, x);
    }
    // B: tensor-core flash attention (q-tile 128, depth-2 ring)
    {
        dim3 grid(N_POS / 128, HEADS, BATCH);
        attn_tc_kernel<<<grid, 256>>>();
    }
    // C: y = w_out @ att + b_out   (split-at-staging tf32 MMA)
    {
        dim3 grid(N_POS / 64, C_IN / 64, BATCH);
        gemm_out_kernel<<<grid, 256>>>(w_out, y, b_out);
    }
}

// round 13
// speedup vs baseline: 1.2099x; 1.1690x over previous
#include <cuda_runtime.h>
#include <cstdint>

#define N_POS   4096
#define HEADS   4
#define DHEAD   32
#define C_IN    256
#define HID     128          // HEADS*DHEAD
#define BATCH   4
#define SCALE   10.0f

// Scratch (no cudaMalloc allowed): qkv [b][3*128][n], attn-out [b][128][n]
__device__ float g_qkv[(size_t)BATCH * 3 * HID * N_POS];   // 25.2 MB
__device__ float g_att[(size_t)BATCH * HID * N_POS];       //  8.4 MB

#define FULLM  0xffffffffu

__device__ __forceinline__ uint32_t f2tf(float x) {
    uint32_t r;
    asm("cvt.rna.tf32.f32 %0, %1;" : "=r"(r) : "f"(x));
    return r;
}

// pack two fp32 into half2: lo -> low half, hi -> high half
__device__ __forceinline__ uint32_t pack_h2(float lo, float hi) {
    uint32_t r;
    asm("cvt.rn.f16x2.f32 %0, %1, %2;" : "=r"(r) : "f"(hi), "f"(lo));
    return r;
}

__device__ __forceinline__ void mma_tf32(float d[4], const uint32_t a[4],
                                         const uint32_t b[2]) {
    asm volatile(
        "mma.sync.aligned.m16n8k8.row.col.f32.tf32.tf32.f32 "
        "{%0,%1,%2,%3}, {%4,%5,%6,%7}, {%8,%9}, {%0,%1,%2,%3};"
        : "+f"(d[0]), "+f"(d[1]), "+f"(d[2]), "+f"(d[3])
        : "r"(a[0]), "r"(a[1]), "r"(a[2]), "r"(a[3]), "r"(b[0]), "r"(b[1]));
}

__device__ __forceinline__ void mma_f16(float d[4], const uint32_t a[4],
                                        const uint32_t b[2]) {
    asm volatile(
        "mma.sync.aligned.m16n8k16.row.col.f32.f16.f16.f32 "
        "{%0,%1,%2,%3}, {%4,%5,%6,%7}, {%8,%9}, {%0,%1,%2,%3};"
        : "+f"(d[0]), "+f"(d[1]), "+f"(d[2]), "+f"(d[3])
        : "r"(a[0]), "r"(a[1]), "r"(a[2]), "r"(a[3]), "r"(b[0]), "r"(b[1]));
}

__device__ __forceinline__ void cp_async16(void* smem_dst, const void* gsrc) {
    uint32_t s = (uint32_t)__cvta_generic_to_shared(smem_dst);
    asm volatile("cp.async.cg.shared.global [%0], [%1], 16;\n"
                 :: "r"(s), "l"(gsrc) : "memory");
}

// ---------------------------------------------------------------------------
// Projection GEMM: tensor-core, 3-term tf32 split, (hi,lo) packed as uint2 so
// every fragment element is ONE LDS.64. Register double-buffer prefetch, one
// sync per k-tile. Optional fused per-column L2-norm over 32-row (d) groups.
//   Y[b][o][i] = sum_c W[o][c] X[b][c][i] (+ bias[o])
// uint2 strides: WS_STR=20, XS_STR=68 (both === 4 mod 16 -> conflict-free
// 64-bit bank-pairs for both fragment patterns).
// ---------------------------------------------------------------------------
#define WS_STR 20
#define XS_STR 68

template <bool DO_NORM>
__device__ __forceinline__ void gemm_tc_body(
    const float* __restrict__ W, const float* __restrict__ X,
    float* __restrict__ Y, const float* __restrict__ bias,
    int K, long xstride_b, long ystride_b)
{
    __shared__ uint2 WsP[2][64 * WS_STR];   // (hi, lo) tf32 pairs
    __shared__ uint2 XsP[2][16 * XS_STR];
    __shared__ float nrm[128];              // [group 0..1][col 0..63]

    const int b  = blockIdx.z;
    const int o0 = blockIdx.y * 64;
    const int i0 = blockIdx.x * 64;
    const float* Xb = X + (long)b * xstride_b;
    float*       Yb = Y + (long)b * ystride_b;

    const int tid  = threadIdx.x;
    const int wid  = tid >> 5;
    const int lane = tid & 31;
    const int gid  = lane >> 2;
    const int tig  = lane & 3;
    const int wq   = wid >> 1;
    const int wn   = wid & 1;

    const int wo = tid >> 2;              // staging: W row (0..63)
    const int wc = (tid & 3) * 4;         // staging: W col group
    const int xc = tid >> 4;              // staging: X row (0..15)
    const int xi = (tid & 15) * 4;        // staging: X col group

    const int KT = K / 16;

    float4 wreg, xreg;

    auto split1 = [](float v) -> uint2 {
        uint2 r;
        r.x = f2tf(v);
        r.y = f2tf(v - __uint_as_float(r.x));
        return r;
    };
    auto stage_split = [&](int s) {
        uint2 w0 = split1(wreg.x), w1 = split1(wreg.y);
        uint2 w2 = split1(wreg.z), w3 = split1(wreg.w);
        *(uint4*)&WsP[s][wo * WS_STR + wc]     = make_uint4(w0.x, w0.y, w1.x, w1.y);
        *(uint4*)&WsP[s][wo * WS_STR + wc + 2] = make_uint4(w2.x, w2.y, w3.x, w3.y);
        uint2 x0 = split1(xreg.x), x1 = split1(xreg.y);
        uint2 x2 = split1(xreg.z), x3 = split1(xreg.w);
        *(uint4*)&XsP[s][xc * XS_STR + xi]     = make_uint4(x0.x, x0.y, x1.x, x1.y);
        *(uint4*)&XsP[s][xc * XS_STR + xi + 2] = make_uint4(x2.x, x2.y, x3.x, x3.y);
    };
    auto load_tile = [&](int kt) {
        const int k0 = kt * 16;
        wreg = *(const float4*)&W[(long)(o0 + wo) * K + k0 + wc];
        xreg = *(const float4*)&Xb[(long)(k0 + xc) * N_POS + i0 + xi];
    };

    // prologue: tile 0 staged, tile 1 in regs
    load_tile(0);
    stage_split(0);
    if (KT > 1) load_tile(1);
    if (DO_NORM && tid < 128) nrm[tid] = 0.0f;
    __syncthreads();

    float acc[4][4] = {};

    for (int kt = 0; kt < KT; kt++) {
        const int s = kt & 1;
        if (kt + 1 < KT) {
            stage_split(s ^ 1);                  // STS tile kt+1
            if (kt + 2 < KT) load_tile(kt + 2);  // LDG tile kt+2 -> regs
        }

        #pragma unroll
        for (int kk = 0; kk < 2; kk++) {
            const int ar = wq * 16 + gid;
            const int ac = kk * 8 + tig;
            uint2 A0 = WsP[s][ar * WS_STR + ac];
            uint2 A1 = WsP[s][(ar + 8) * WS_STR + ac];
            uint2 A2 = WsP[s][ar * WS_STR + ac + 4];
            uint2 A3 = WsP[s][(ar + 8) * WS_STR + ac + 4];
            uint32_t aH[4] = {A0.x, A1.x, A2.x, A3.x};
            uint32_t aL[4] = {A0.y, A1.y, A2.y, A3.y};
            #pragma unroll
            for (int nt = 0; nt < 4; nt++) {
                const int col = wn * 32 + nt * 8 + gid;
                const int cr  = kk * 8 + tig;
                uint2 B0 = XsP[s][cr * XS_STR + col];
                uint2 B1 = XsP[s][(cr + 4) * XS_STR + col];
                uint32_t bH[2] = {B0.x, B1.x};
                uint32_t bL[2] = {B0.y, B1.y};
                mma_tf32(acc[nt], aH, bH);
                mma_tf32(acc[nt], aH, bL);
                mma_tf32(acc[nt], aL, bH);
            }
        }
        __syncthreads();
    }

    if (DO_NORM && o0 < 2 * HID) {
        // fused L2-norm: sum of squares over each 32-row (d) group, per column
        const int g = wq >> 1;
        float p0[4], p1[4];
        #pragma unroll
        for (int nt = 0; nt < 4; nt++) {
            p0[nt] = acc[nt][0] * acc[nt][0] + acc[nt][2] * acc[nt][2];
            p1[nt] = acc[nt][1] * acc[nt][1] + acc[nt][3] * acc[nt][3];
            #pragma unroll
            for (int m = 4; m < 32; m <<= 1) {
                p0[nt] += __shfl_xor_sync(FULLM, p0[nt], m);
                p1[nt] += __shfl_xor_sync(FULLM, p1[nt], m);
            }
        }
        if (lane < 4) {
            #pragma unroll
            for (int nt = 0; nt < 4; nt++) {
                const int col = wn * 32 + nt * 8 + 2 * tig;
                atomicAdd(&nrm[g * 64 + col],     p0[nt]);
                atomicAdd(&nrm[g * 64 + col + 1], p1[nt]);
            }
        }
        __syncthreads();
        #pragma unroll
        for (int nt = 0; nt < 4; nt++) {
            const int col = wn * 32 + nt * 8 + 2 * tig;
            float i0v = 1.0f / fmaxf(sqrtf(nrm[g * 64 + col]),     1e-12f);
            float i1v = 1.0f / fmaxf(sqrtf(nrm[g * 64 + col + 1]), 1e-12f);
            acc[nt][0] *= i0v; acc[nt][2] *= i0v;
            acc[nt][1] *= i1v; acc[nt][3] *= i1v;
        }
    }

    const int orow = o0 + wq * 16 + gid;
    const float b0 = bias ? bias[orow]     : 0.0f;
    const float b1 = bias ? bias[orow + 8] : 0.0f;
    #pragma unroll
    for (int nt = 0; nt < 4; nt++) {
        const int col = i0 + wn * 32 + nt * 8 + 2 * tig;
        float2 lo, hi;
        lo.x = acc[nt][0] + b0; lo.y = acc[nt][1] + b0;
        hi.x = acc[nt][2] + b1; hi.y = acc[nt][3] + b1;
        *(float2*)&Yb[(long)orow * N_POS + col]       = lo;
        *(float2*)&Yb[(long)(orow + 8) * N_POS + col] = hi;
    }
}

__global__ __launch_bounds__(256) void gemm_qkv_kernel(
    const float* __restrict__ W, const float* __restrict__ X)
{
    gemm_tc_body<true>(W, X, g_qkv, nullptr, C_IN,
                       (long)C_IN * N_POS, (long)3 * HID * N_POS);
}

__global__ __launch_bounds__(256) void gemm_out_kernel(
    const float* __restrict__ W, float* __restrict__ Y,
    const float* __restrict__ bias)
{
    gemm_tc_body<false>(W, g_att, Y, bias, HID,
                        (long)HID * N_POS, (long)C_IN * N_POS);
}

// ---------------------------------------------------------------------------
// Tensor-core flash attention.
//  GEMM1 (QK'): tf32 m16n8k8, Q fragments in registers (loaded once).
//  Softmax: p = exp(10*s), NO shift (s in [-1,1] -> p in [e-10, e10=22026],
//           inside fp16 normal range both ends; l >= 1 guaranteed by s_ii=1).
//  GEMM2 (PV'): fp16 m16n8k16 — the m16n8k8 C-fragment (row gid/gid+8, cols
//           2tig,2tig+1) IS the fp16 A-fragment layout, so P packs with
//           cvt.rn.f16x2.f32 only: no shuffles. V via LDS.64 + 1 cvt.
//  K/V staged fp32 via 2-stage cp.async ring (wait_group 1, refill at end).
// Block = (b, h, 128-query tile), 8 warps (wq 0..3 x wn 0..1), 512 blocks.
// ---------------------------------------------------------------------------
#define KS_STR 72     // b-frag bank = 8*tig+gid, distinct
#define VS_STR 68     // fp32 row stride; float2 loads 8B-aligned
#define OS_STR 136
#define PB_STR 33
#define STG_WORDS (32 * KS_STR + 32 * VS_STR)   // 4480 floats per stage

__global__ __launch_bounds__(256, 2) void attn_tc_kernel()
{
    __shared__ float SB[2 * STG_WORDS];   // K/V ring; aliased by epilogue
    __shared__ float sh_l[128];

    const int b   = blockIdx.z;
    const int h   = blockIdx.y;
    const int q0  = blockIdx.x * 128;
    const int tid = threadIdx.x;
    const int wid  = tid >> 5;
    const int lane = tid & 31;
    const int gid  = lane >> 2;
    const int tig  = lane & 3;
    const int wq   = wid >> 1;   // 0..3 : 32-row q group
    const int wn   = wid & 1;    // 0..1 : j/k half

    const float* qb = g_qkv + ((long)(b * 3 + 0) * HID + h * DHEAD) * N_POS;
    const float* kb = g_qkv + ((long)(b * 3 + 1) * HID + h * DHEAD) * N_POS;
    const float* vb = g_qkv + ((long)(b * 3 + 2) * HID + h * DHEAD) * N_POS;

    float* Ks0 = SB;
    float* Vs0 = SB + 32 * KS_STR;
    float* Ks1 = SB + STG_WORDS;
    float* Vs1 = SB + STG_WORDS + 32 * KS_STR;

    // ---- stage tiles 0 and 1 ----
    #pragma unroll
    for (int r = 0; r < 2; r++) {
        int c = tid + r * 256;
        int d = c >> 4, j4 = (c & 15) * 4;
        cp_async16(Ks0 + d * KS_STR + j4, kb + (long)d * N_POS + j4);
        cp_async16(Vs0 + d * VS_STR + j4, vb + (long)d * N_POS + j4);
    }
    asm volatile("cp.async.commit_group;\n" ::: "memory");
    #pragma unroll
    for (int r = 0; r < 2; r++) {
        int c = tid + r * 256;
        int d = c >> 4, j4 = (c & 15) * 4;
        cp_async16(Ks1 + d * KS_STR + j4, kb + (long)d * N_POS + 64 + j4);
        cp_async16(Vs1 + d * VS_STR + j4, vb + (long)d * N_POS + 64 + j4);
    }
    asm volatile("cp.async.commit_group;\n" ::: "memory");

    // ---- Q fragments in registers (one-time) ----
    uint32_t qf[2][4][4];
    #pragma unroll
    for (int mt = 0; mt < 2; mt++) {
        const int row = wq * 32 + mt * 16 + gid;
        const float* qp = qb + q0 + row;
        #pragma unroll
        for (int kk = 0; kk < 4; kk++) {
            qf[mt][kk][0] = f2tf(qp[(long)(kk * 8 + tig) * N_POS]);
            qf[mt][kk][1] = f2tf(qp[(long)(kk * 8 + tig) * N_POS + 8]);
            qf[mt][kk][2] = f2tf(qp[(long)(kk * 8 + tig + 4) * N_POS]);
            qf[mt][kk][3] = f2tf(qp[(long)(kk * 8 + tig + 4) * N_POS + 8]);
        }
    }
    if (tid < 128) sh_l[tid] = 0.0f;

    float O[2][4][4] = {};
    float l_lo[2] = {}, l_hi[2] = {};

    for (int it = 0; it < N_POS / 64; it++) {
        const int s = it & 1;
        float* KsS = s ? Ks1 : Ks0;
        float* VsS = s ? Vs1 : Vs0;

        asm volatile("cp.async.wait_group 1;\n" ::: "memory");
        __syncthreads();   // tile it visible to all; also fences Q/sh_l init

        // ---- GEMM1: S[32q x 32j] = Q K'  (tf32) ----
        float S[2][4][4] = {};
        #pragma unroll
        for (int kk = 0; kk < 4; kk++) {
            const int c0 = kk * 8 + tig;
            #pragma unroll
            for (int nt = 0; nt < 4; nt++) {
                const int col = wn * 32 + nt * 8 + gid;
                uint32_t bb[2];
                bb[0] = f2tf(KsS[c0 * KS_STR + col]);
                bb[1] = f2tf(KsS[(c0 + 4) * KS_STR + col]);
                mma_tf32(S[0][nt], qf[0][kk], bb);
                mma_tf32(S[1][nt], qf[1][kk], bb);
            }
        }

        // ---- P = exp(10*s) (no shift); accumulate l ----
        #pragma unroll
        for (int mt = 0; mt < 2; mt++)
            #pragma unroll
            for (int nt = 0; nt < 4; nt++) {
                S[mt][nt][0] = __expf(S[mt][nt][0] * SCALE);
                S[mt][nt][1] = __expf(S[mt][nt][1] * SCALE);
                S[mt][nt][2] = __expf(S[mt][nt][2] * SCALE);
                S[mt][nt][3] = __expf(S[mt][nt][3] * SCALE);
                l_lo[mt] += S[mt][nt][0] + S[mt][nt][1];
                l_hi[mt] += S[mt][nt][2] + S[mt][nt][3];
            }

        // ---- GEMM2: O += P V'  (fp16 m16n8k16, no shuffles) ----
        #pragma unroll
        for (int kk2 = 0; kk2 < 2; kk2++) {
            const int g = kk2 * 2;
            uint32_t a0[4], a1[4];
            a0[0] = pack_h2(S[0][g][0],     S[0][g][1]);
            a0[1] = pack_h2(S[0][g][2],     S[0][g][3]);
            a0[2] = pack_h2(S[0][g + 1][0], S[0][g + 1][1]);
            a0[3] = pack_h2(S[0][g + 1][2], S[0][g + 1][3]);
            a1[0] = pack_h2(S[1][g][0],     S[1][g][1]);
            a1[1] = pack_h2(S[1][g][2],     S[1][g][3]);
            a1[2] = pack_h2(S[1][g + 1][0], S[1][g + 1][1]);
            a1[3] = pack_h2(S[1][g + 1][2], S[1][g + 1][3]);
            const int kbase = wn * 32 + kk2 * 16;
            #pragma unroll
            for (int dt = 0; dt < 4; dt++) {
                const int dcol = dt * 8 + gid;
                float2 v0 = *(const float2*)&VsS[dcol * VS_STR + kbase + 2 * tig];
                float2 v1 = *(const float2*)&VsS[dcol * VS_STR + kbase + 2 * tig + 8];
                uint32_t bb[2];
                bb[0] = pack_h2(v0.x, v0.y);
                bb[1] = pack_h2(v1.x, v1.y);
                mma_f16(O[0][dt], a0, bb);
                mma_f16(O[1][dt], a1, bb);
            }
        }

        __syncthreads();   // all warps done with this stage's smem

        // refill this stage with tile it+2 (or commit an empty group)
        if (it + 2 < N_POS / 64) {
            const int j0 = (it + 2) * 64;
            #pragma unroll
            for (int r = 0; r < 2; r++) {
                int c = tid + r * 256;
                int d = c >> 4, j4 = (c & 15) * 4;
                cp_async16(KsS + d * KS_STR + j4, kb + (long)d * N_POS + j0 + j4);
                cp_async16(VsS + d * VS_STR + j4, vb + (long)d * N_POS + j0 + j4);
            }
        }
        asm volatile("cp.async.commit_group;\n" ::: "memory");
    }

    // ---- reduce l ----
    #pragma unroll
    for (int mt = 0; mt < 2; mt++) {
        l_lo[mt] += __shfl_xor_sync(FULLM, l_lo[mt], 1);
        l_lo[mt] += __shfl_xor_sync(FULLM, l_lo[mt], 2);
        l_hi[mt] += __shfl_xor_sync(FULLM, l_hi[mt], 1);
        l_hi[mt] += __shfl_xor_sync(FULLM, l_hi[mt], 2);
        if (tig == 0) {
            atomicAdd(&sh_l[wq * 32 + mt * 16 + gid],     l_lo[mt]);
            atomicAdd(&sh_l[wq * 32 + mt * 16 + gid + 8], l_hi[mt]);
        }
    }
    __syncthreads();   // l complete; all warps past ring reads

    // ---- merge k-half partials via smem (aliases the K/V ring) ----
    float* Os = SB;                 // [32 d][OS_STR]
    float* PB = SB + 32 * OS_STR;   // [128 q][PB_STR]

    if (wn == 1) {
        #pragma unroll
        for (int mt = 0; mt < 2; mt++) {
            const int row = wq * 32 + mt * 16 + gid;
            #pragma unroll
            for (int nt = 0; nt < 4; nt++) {
                const int col = nt * 8 + 2 * tig;
                PB[row * PB_STR + col]           = O[mt][nt][0];
                PB[row * PB_STR + col + 1]       = O[mt][nt][1];
                PB[(row + 8) * PB_STR + col]     = O[mt][nt][2];
                PB[(row + 8) * PB_STR + col + 1] = O[mt][nt][3];
            }
        }
    }
    __syncthreads();
    if (wn == 0) {
        #pragma unroll
        for (int mt = 0; mt < 2; mt++) {
            const int row = wq * 32 + mt * 16 + gid;
            const float invl_lo = 1.0f / sh_l[row];
            const float invl_hi = 1.0f / sh_l[row + 8];
            #pragma unroll
            for (int nt = 0; nt < 4; nt++) {
                const int col = nt * 8 + 2 * tig;
                float o0 = (O[mt][nt][0] + PB[row * PB_STR + col])           * invl_lo;
                float o1 = (O[mt][nt][1] + PB[row * PB_STR + col + 1])       * invl_lo;
                float o2 = (O[mt][nt][2] + PB[(row + 8) * PB_STR + col])     * invl_hi;
                float o3 = (O[mt][nt][3] + PB[(row + 8) * PB_STR + col + 1]) * invl_hi;
                Os[col * OS_STR + row]           = o0;
                Os[(col + 1) * OS_STR + row]     = o1;
                Os[col * OS_STR + row + 8]       = o2;
                Os[(col + 1) * OS_STR + row + 8] = o3;
            }
        }
    }
    __syncthreads();

    float* ob = g_att + ((long)b * HID + h * DHEAD) * N_POS + q0;
    #pragma unroll
    for (int r = 0; r < 16; r++) {
        int idx = tid + r * 256;
        int d = idx >> 7, qi = idx & 127;
        ob[(long)d * N_POS + qi] = Os[d * OS_STR + qi];
    }
}

// ---------------------------------------------------------------------------
extern "C" void kernel_launch(void* const* d_in, const int* in_sizes, int n_in,
                              void* d_out, int out_size)
{
    const float* x     = (const float*)d_in[0];   // [4,256,64,64]
    const float* w_qkv = (const float*)d_in[1];   // [384,256]
    const float* w_out = (const float*)d_in[2];   // [256,128]
    const float* b_out = (const float*)d_in[3];   // [256]
    float* y = (float*)d_out;                     // [4,256,64,64]

    // A: qkv = w_qkv @ x   (packed-split tf32 MMA + fused q/k L2-norm)
    {
        dim3 grid(N_POS / 64, (3 * HID) / 64, BATCH);
        gemm_qkv_kernel<<<grid, 256>>>(w_qkv, x);
    }
    // B: tensor-core flash attention (tf32 QK', fp16 PV')
    {
        dim3 grid(N_POS / 128, HEADS, BATCH);
        attn_tc_kernel<<<grid, 256>>>();
    }
    // C: y = w_out @ att + b_out   (packed-split tf32 MMA)
    {
        dim3 grid(N_POS / 64, C_IN / 64, BATCH);
        gemm_out_kernel<<<grid, 256>>>(w_out, y, b_out);
    }
}